// round 5
// baseline (speedup 1.0000x reference)
#include <cuda_runtime.h>
#include <limits.h>

// Problem constants (fixed by setup_inputs)
#define NMAX   50000
#define EMAX   800000
#define ETOTMX (EMAX + NMAX)
#define HDIM   64
#define FIN    768
#define NGRAPH 512
#define NEG_SLOPE 0.2f

// ---------------- scratch (device globals; float4 => 16B alignment) ----------------
__device__ float4 g_h1v  [NMAX * HDIM / 4];   // x @ W1
__device__ float4 g_out1v[NMAX * HDIM / 4];   // layer-1 aggregation (+b1)
__device__ float4 g_h2v  [NMAX * HDIM / 4];   // relu(out1) @ W2
__device__ float4 g_out2v[NMAX * HDIM / 4];   // layer-2 aggregation (+b2)
__device__ float4 g_pooledv[NGRAPH * HDIM / 4];
__device__ float  g_as[NMAX];
__device__ float  g_ad[NMAX];
__device__ float  g_denom[NMAX];
__device__ int    g_m[NMAX];
__device__ float  g_ew[ETOTMX];
__device__ int    g_src[ETOTMX];
__device__ int    g_dst[ETOTMX];
__device__ int    g_batch[NMAX];
__device__ float  g_cnt[NGRAPH];
__device__ int    g_is64;

// ---------------- helpers ----------------
__device__ __forceinline__ int   f2ord(float v) {
    int b = __float_as_int(v);
    return b >= 0 ? b : (b ^ 0x7fffffff);
}
__device__ __forceinline__ float ord2f(int b) {
    return __int_as_float(b >= 0 ? b : (b ^ 0x7fffffff));
}
__device__ __forceinline__ void red_add_v4(float* addr, float4 v) {
    asm volatile("red.global.add.v4.f32 [%0], {%1,%2,%3,%4};"
                 :: "l"(addr), "f"(v.x), "f"(v.y), "f"(v.z), "f"(v.w) : "memory");
}

// ---------------- kernels ----------------

// Detect whether the index buffers are int64 or int32.
// If int64: high 32-bit word of every element is 0 (values in [0, 50000)).
// If int32: odd words are random node ids, virtually surely nonzero somewhere.
__global__ void k_detect(const int* __restrict__ ei_words, int E) {
    __shared__ int any;
    if (threadIdx.x == 0) any = 0;
    __syncthreads();
    int acc = 0;
    int probe = E < 2048 ? E : 2048;
    for (int i = threadIdx.x; i < probe; i += blockDim.x)
        acc |= ei_words[2 * i + 1];
    if (acc) atomicOr(&any, 1);
    __syncthreads();
    if (threadIdx.x == 0) g_is64 = (any == 0) ? 1 : 0;
}

// Build int32 src/dst with self-loops appended; convert batch ids.
__global__ void k_prep(const void* __restrict__ ei_raw,
                       const void* __restrict__ batch_raw, int E, int N) {
    int i = blockIdx.x * blockDim.x + threadIdx.x;
    const bool is64 = (g_is64 != 0);
    if (i < E) {
        if (is64) {
            const long long* e = (const long long*)ei_raw;
            g_src[i] = (int)e[i];
            g_dst[i] = (int)e[(size_t)E + i];
        } else {
            const int* e = (const int*)ei_raw;
            g_src[i] = e[i];
            g_dst[i] = e[E + i];
        }
    } else if (i < E + N) {
        g_src[i] = i - E;
        g_dst[i] = i - E;
    }
    if (i < N) {
        g_batch[i] = is64 ? (int)((const long long*)batch_raw)[i]
                          : ((const int*)batch_raw)[i];
    }
}

// Tiled fp32 GEMM: h[N,64] = act(x[N,K]) @ W[K,64].  K % 32 == 0.
// Block: 64 rows x 64 cols, 256 threads, 4x4 register tile each.
template <bool RELU_IN>
__global__ __launch_bounds__(256) void k_gemm64(const float* __restrict__ x,
                                                const float* __restrict__ W,
                                                float* __restrict__ h,
                                                int N, int K) {
    __shared__ float xs[32][68];   // [k][row]
    __shared__ float ws[32][64];   // [k][col]

    const int tid = threadIdx.x;
    const int tx = tid & 15;       // cols tx*4 .. tx*4+3
    const int ty = tid >> 4;       // rows ty*4 .. ty*4+3
    const int row0 = blockIdx.x * 64;

    float acc[4][4] = {};

    for (int k0 = 0; k0 < K; k0 += 32) {
        #pragma unroll
        for (int i = 0; i < 2; i++) {
            int idx = tid + i * 256;          // 0..511
            int r   = idx >> 3;               // 0..63
            int k4  = (idx & 7) * 4;          // 0,4,..28
            float4 v = make_float4(0.f, 0.f, 0.f, 0.f);
            if (row0 + r < N)
                v = *(const float4*)&x[(size_t)(row0 + r) * K + k0 + k4];
            if (RELU_IN) {
                v.x = fmaxf(v.x, 0.f); v.y = fmaxf(v.y, 0.f);
                v.z = fmaxf(v.z, 0.f); v.w = fmaxf(v.w, 0.f);
            }
            xs[k4 + 0][r] = v.x; xs[k4 + 1][r] = v.y;
            xs[k4 + 2][r] = v.z; xs[k4 + 3][r] = v.w;
        }
        #pragma unroll
        for (int i = 0; i < 2; i++) {
            int idx = tid + i * 256;
            int kk  = idx >> 4;               // 0..31
            int n4  = (idx & 15) * 4;         // 0..60
            *(float4*)&ws[kk][n4] = *(const float4*)&W[(size_t)(k0 + kk) * HDIM + n4];
        }
        __syncthreads();

        #pragma unroll
        for (int kk = 0; kk < 32; kk++) {
            float4 a = *(const float4*)&xs[kk][ty * 4];
            float4 b = *(const float4*)&ws[kk][tx * 4];
            acc[0][0] += a.x * b.x; acc[0][1] += a.x * b.y; acc[0][2] += a.x * b.z; acc[0][3] += a.x * b.w;
            acc[1][0] += a.y * b.x; acc[1][1] += a.y * b.y; acc[1][2] += a.y * b.z; acc[1][3] += a.y * b.w;
            acc[2][0] += a.z * b.x; acc[2][1] += a.z * b.y; acc[2][2] += a.z * b.z; acc[2][3] += a.z * b.w;
            acc[3][0] += a.w * b.x; acc[3][1] += a.w * b.y; acc[3][2] += a.w * b.z; acc[3][3] += a.w * b.w;
        }
        __syncthreads();
    }

    #pragma unroll
    for (int i = 0; i < 4; i++) {
        int r = row0 + ty * 4 + i;
        if (r < N) {
            float4 o = make_float4(acc[i][0], acc[i][1], acc[i][2], acc[i][3]);
            *(float4*)&h[(size_t)r * HDIM + tx * 4] = o;
        }
    }
}

// a_s[r] = h[r,:] . att_s ; a_d[r] = h[r,:] . att_d.  16 lanes per row.
__global__ void k_attn_coef(const float* __restrict__ h,
                            const float* __restrict__ att_s,
                            const float* __restrict__ att_d, int N) {
    int t = blockIdx.x * blockDim.x + threadIdx.x;
    int r = t >> 4;
    int l = t & 15;
    if (r >= N) return;
    float4 v  = *(const float4*)&h[(size_t)r * HDIM + l * 4];
    float4 s4 = *(const float4*)&att_s[l * 4];
    float4 d4 = *(const float4*)&att_d[l * 4];
    float s = v.x * s4.x + v.y * s4.y + v.z * s4.z + v.w * s4.w;
    float d = v.x * d4.x + v.y * d4.y + v.z * d4.z + v.w * d4.w;
    #pragma unroll
    for (int off = 8; off > 0; off >>= 1) {
        s += __shfl_down_sync(0xffffffffu, s, off, 16);
        d += __shfl_down_sync(0xffffffffu, d, off, 16);
    }
    if (l == 0) { g_as[r] = s; g_ad[r] = d; }
}

// init per-layer: out <- bias broadcast, m <- -inf key, denom <- 0
__global__ void k_init_layer(float* __restrict__ out, const float* __restrict__ bias, int N) {
    int t = blockIdx.x * blockDim.x + threadIdx.x;
    if (t < N * HDIM) out[t] = bias[t & (HDIM - 1)];
    if (t < N) { g_m[t] = INT_MIN; g_denom[t] = 0.f; }
}

// pass A: e = leakyrelu(a_s[src]+a_d[dst]); segment max by dst
__global__ void k_edge_max(int Etot) {
    int i = blockIdx.x * blockDim.x + threadIdx.x;
    if (i >= Etot) return;
    float v = g_as[g_src[i]] + g_ad[g_dst[i]];
    v = v >= 0.f ? v : NEG_SLOPE * v;
    g_ew[i] = v;
    atomicMax(&g_m[g_dst[i]], f2ord(v));
}

// pass B: w = exp(e - m[dst]); segment sum by dst
__global__ void k_edge_exp(int Etot) {
    int i = blockIdx.x * blockDim.x + threadIdx.x;
    if (i >= Etot) return;
    int d = g_dst[i];
    float w = __expf(g_ew[i] - ord2f(g_m[d]));
    g_ew[i] = w;
    atomicAdd(&g_denom[d], w);
}

// pass C: out[dst] += (w/denom[dst]) * h[src].  16 lanes per edge, float4 each.
__global__ void k_edge_agg(const float* __restrict__ h, float* __restrict__ out, int Etot) {
    int t = blockIdx.x * blockDim.x + threadIdx.x;
    int e = t >> 4;
    int l = t & 15;
    if (e >= Etot) return;
    int s = g_src[e], d = g_dst[e];
    float alpha = g_ew[e] / g_denom[d];
    float4 v = *(const float4*)&h[(size_t)s * HDIM + l * 4];
    v.x *= alpha; v.y *= alpha; v.z *= alpha; v.w *= alpha;
    red_add_v4(&out[(size_t)d * HDIM + l * 4], v);
}

__global__ void k_pool_init() {
    int t = blockIdx.x * blockDim.x + threadIdx.x;
    if (t < NGRAPH * HDIM) ((float*)g_pooledv)[t] = 0.f;
    if (t < NGRAPH) g_cnt[t] = 0.f;
}

// mean pool of relu(out2) by graph id. 16 lanes per node.
__global__ void k_pool(const float* __restrict__ h, int N) {
    int t = blockIdx.x * blockDim.x + threadIdx.x;
    int r = t >> 4;
    int l = t & 15;
    if (r >= N) return;
    int g = g_batch[r];
    float4 v = *(const float4*)&h[(size_t)r * HDIM + l * 4];
    v.x = fmaxf(v.x, 0.f); v.y = fmaxf(v.y, 0.f);
    v.z = fmaxf(v.z, 0.f); v.w = fmaxf(v.w, 0.f);
    red_add_v4(&((float*)g_pooledv)[(size_t)g * HDIM + l * 4], v);
    if (l == 0) atomicAdd(&g_cnt[g], 1.0f);
}

// head: out[g, 0:2] = (pooled[g]/cnt[g]) @ Wlin + blin
__global__ void k_head(const float* __restrict__ Wlin, const float* __restrict__ blin,
                       float* __restrict__ out) {
    int g = blockIdx.x * blockDim.x + threadIdx.x;
    if (g >= NGRAPH) return;
    const float* pooled = (const float*)g_pooledv;
    float inv = 1.0f / fmaxf(g_cnt[g], 1.0f);
    float a0 = 0.f, a1 = 0.f;
    #pragma unroll
    for (int k = 0; k < HDIM; k++) {
        float p = pooled[g * HDIM + k] * inv;
        a0 += p * Wlin[k * 2 + 0];
        a1 += p * Wlin[k * 2 + 1];
    }
    out[g * 2 + 0] = a0 + blin[0];
    out[g * 2 + 1] = a1 + blin[1];
}

// ---------------- launch ----------------
extern "C" void kernel_launch(void* const* d_in, const int* in_sizes, int n_in,
                              void* d_out, int out_size) {
    const float* x    = (const float*)d_in[0];
    const void*  ei   = d_in[1];
    const void*  batch= d_in[2];
    const float* W1   = (const float*)d_in[3];
    const float* asr1 = (const float*)d_in[4];
    const float* adt1 = (const float*)d_in[5];
    const float* b1   = (const float*)d_in[6];
    const float* W2   = (const float*)d_in[7];
    const float* asr2 = (const float*)d_in[8];
    const float* adt2 = (const float*)d_in[9];
    const float* b2   = (const float*)d_in[10];
    const float* Wlin = (const float*)d_in[11];
    const float* blin = (const float*)d_in[12];
    float* out = (float*)d_out;

    const int N = in_sizes[2];            // batch length
    const int E = in_sizes[1] / 2;        // edge_index has 2*E elements
    const int Etot = E + N;

    float* h1   = (float*)g_h1v;
    float* out1 = (float*)g_out1v;
    float* h2   = (float*)g_h2v;
    float* out2 = (float*)g_out2v;

    const int T = 256;
    dim3 gPrep((Etot + T - 1) / T);
    dim3 gGemm((N + 63) / 64);
    dim3 gRow16((N * 16 + T - 1) / T);
    dim3 gNH((N * HDIM + T - 1) / T);
    dim3 gE((Etot + T - 1) / T);
    dim3 gE16((int)(((long long)Etot * 16 + T - 1) / T));

    k_detect<<<1, 256>>>((const int*)ei, E);
    k_prep<<<gPrep, T>>>(ei, batch, E, N);

    // ---- layer 1 ----
    k_gemm64<false><<<gGemm, T>>>(x, W1, h1, N, FIN);
    k_attn_coef<<<gRow16, T>>>(h1, asr1, adt1, N);
    k_init_layer<<<gNH, T>>>(out1, b1, N);
    k_edge_max<<<gE, T>>>(Etot);
    k_edge_exp<<<gE, T>>>(Etot);
    k_edge_agg<<<gE16, T>>>(h1, out1, Etot);

    // ---- layer 2 (relu fused into GEMM input) ----
    k_gemm64<true><<<gGemm, T>>>(out1, W2, h2, N, HDIM);
    k_attn_coef<<<gRow16, T>>>(h2, asr2, adt2, N);
    k_init_layer<<<gNH, T>>>(out2, b2, N);
    k_edge_max<<<gE, T>>>(Etot);
    k_edge_exp<<<gE, T>>>(Etot);
    k_edge_agg<<<gE16, T>>>(h2, out2, Etot);

    // ---- pool + head (relu fused into pool) ----
    k_pool_init<<<(NGRAPH * HDIM + T - 1) / T, T>>>();
    k_pool<<<gRow16, T>>>(out2, N);
    k_head<<<(NGRAPH + T - 1) / T, T>>>(Wlin, blin, out);
}

// round 7
// speedup vs baseline: 2.5122x; 2.5122x over previous
#include <cuda_runtime.h>
#include <limits.h>
#include <math_constants.h>

// Problem constants (fixed by setup_inputs)
#define NMAX   50000
#define EMAX   800000
#define ETOTMX (EMAX + NMAX)
#define HDIM   64
#define FIN    768
#define NGRAPH 512
#define NEG_SLOPE 0.2f

// ---------------- scratch (device globals; float4 => 16B alignment) ----------------
__device__ float4 g_h1v  [NMAX * HDIM / 4];   // x @ W1
__device__ float4 g_out1v[NMAX * HDIM / 4];   // layer-1 aggregation (+b1)
__device__ float4 g_h2v  [NMAX * HDIM / 4];   // relu(out1) @ W2
__device__ float4 g_out2v[NMAX * HDIM / 4];   // layer-2 aggregation (+b2)
__device__ float  g_as[NMAX];
__device__ float  g_ad[NMAX];
__device__ float  g_ew[ETOTMX];               // scratch e/exp values (deg>32 path)
__device__ int    g_src[ETOTMX];              // original-order src
__device__ int    g_dst[ETOTMX];              // original-order dst
__device__ int    g_deg[NMAX];                // real-edge in-degree
__device__ int    g_off[NMAX + 1];            // CSR offsets (incl. self loop)
__device__ int    g_cur[NMAX];                // scatter cursors
__device__ int    g_csrc[ETOTMX];             // CSR src ids grouped by dst
__device__ int    g_batch[NMAX];
__device__ int    g_is64;

// ---------------- kernels ----------------

// Detect whether the index buffers are int64 or int32.
// int64 values in [0,50000): high word of every element is 0.
// int32: odd words are random node ids -> nonzero somewhere in 2048 probes.
__global__ void k_detect(const int* __restrict__ ei_words, int E) {
    __shared__ int any;
    if (threadIdx.x == 0) any = 0;
    __syncthreads();
    int acc = 0;
    int probe = E < 2048 ? E : 2048;
    for (int i = threadIdx.x; i < probe; i += blockDim.x)
        acc |= ei_words[2 * i + 1];
    if (acc) atomicOr(&any, 1);
    __syncthreads();
    if (threadIdx.x == 0) g_is64 = (any == 0) ? 1 : 0;
}

__global__ void k_zero_deg(int N) {
    int i = blockIdx.x * blockDim.x + threadIdx.x;
    if (i < N) g_deg[i] = 0;
}

// Build int32 src/dst, histogram real-edge dst, convert batch ids.
__global__ void k_prep(const void* __restrict__ ei_raw,
                       const void* __restrict__ batch_raw, int E, int N) {
    int i = blockIdx.x * blockDim.x + threadIdx.x;
    const bool is64 = (g_is64 != 0);
    if (i < E) {
        int s, d;
        if (is64) {
            const long long* e = (const long long*)ei_raw;
            s = (int)e[i];
            d = (int)e[(size_t)E + i];
        } else {
            const int* e = (const int*)ei_raw;
            s = e[i];
            d = e[E + i];
        }
        g_src[i] = s;
        g_dst[i] = d;
        atomicAdd(&g_deg[d], 1);
    }
    if (i < N) {
        g_batch[i] = is64 ? (int)((const long long*)batch_raw)[i]
                          : ((const int*)batch_raw)[i];
    }
}

// Exclusive scan of (deg+1) -> g_off; g_cur = off + 1 (slot 0 = self loop).
__global__ void k_scan(int N) {
    __shared__ int wsum[32];
    __shared__ int carry;
    const int lane = threadIdx.x & 31;
    const int wid  = threadIdx.x >> 5;        // 1024 threads = 32 warps
    if (threadIdx.x == 0) carry = 0;
    __syncthreads();
    for (int base = 0; base < N; base += 1024) {
        int i = base + (int)threadIdx.x;
        int v = (i < N) ? g_deg[i] + 1 : 0;   // +1 for the self loop
        int incl = v;
        #pragma unroll
        for (int o = 1; o < 32; o <<= 1) {
            int t = __shfl_up_sync(0xffffffffu, incl, o);
            if (lane >= o) incl += t;
        }
        if (lane == 31) wsum[wid] = incl;
        __syncthreads();
        if (wid == 0) {
            int s = wsum[lane];
            #pragma unroll
            for (int o = 1; o < 32; o <<= 1) {
                int t = __shfl_up_sync(0xffffffffu, s, o);
                if (lane >= o) s += t;
            }
            wsum[lane] = s;
        }
        __syncthreads();
        int wexcl = (wid == 0) ? 0 : wsum[wid - 1];
        int excl  = carry + wexcl + incl - v;
        if (i < N) { g_off[i] = excl; g_cur[i] = excl + 1; }
        int total = wsum[31];
        __syncthreads();
        if (threadIdx.x == 0) carry += total;
        __syncthreads();
    }
    if (threadIdx.x == 0) g_off[N] = carry;
}

// Scatter edges into CSR buckets; self loops take slot 0 deterministically.
__global__ void k_scatter(int E, int N) {
    int i = blockIdx.x * blockDim.x + threadIdx.x;
    if (i < E) {
        int p = atomicAdd(&g_cur[g_dst[i]], 1);
        g_csrc[p] = g_src[i];
    } else if (i < E + N) {
        int d = i - E;
        g_csrc[g_off[d]] = d;                 // self loop first
    }
}

// Tiled fp32 GEMM: h[N,64] = act(x[N,K]) @ W[K,64].  K % 32 == 0.
template <bool RELU_IN>
__global__ __launch_bounds__(256) void k_gemm64(const float* __restrict__ x,
                                                const float* __restrict__ W,
                                                float* __restrict__ h,
                                                int N, int K) {
    __shared__ float xs[32][68];
    __shared__ float ws[32][64];

    const int tid = threadIdx.x;
    const int tx = tid & 15;
    const int ty = tid >> 4;
    const int row0 = blockIdx.x * 64;

    float acc[4][4] = {};

    for (int k0 = 0; k0 < K; k0 += 32) {
        #pragma unroll
        for (int i = 0; i < 2; i++) {
            int idx = tid + i * 256;
            int r   = idx >> 3;
            int k4  = (idx & 7) * 4;
            float4 v = make_float4(0.f, 0.f, 0.f, 0.f);
            if (row0 + r < N)
                v = *(const float4*)&x[(size_t)(row0 + r) * K + k0 + k4];
            if (RELU_IN) {
                v.x = fmaxf(v.x, 0.f); v.y = fmaxf(v.y, 0.f);
                v.z = fmaxf(v.z, 0.f); v.w = fmaxf(v.w, 0.f);
            }
            xs[k4 + 0][r] = v.x; xs[k4 + 1][r] = v.y;
            xs[k4 + 2][r] = v.z; xs[k4 + 3][r] = v.w;
        }
        #pragma unroll
        for (int i = 0; i < 2; i++) {
            int idx = tid + i * 256;
            int kk  = idx >> 4;
            int n4  = (idx & 15) * 4;
            *(float4*)&ws[kk][n4] = *(const float4*)&W[(size_t)(k0 + kk) * HDIM + n4];
        }
        __syncthreads();

        #pragma unroll
        for (int kk = 0; kk < 32; kk++) {
            float4 a = *(const float4*)&xs[kk][ty * 4];
            float4 b = *(const float4*)&ws[kk][tx * 4];
            acc[0][0] += a.x * b.x; acc[0][1] += a.x * b.y; acc[0][2] += a.x * b.z; acc[0][3] += a.x * b.w;
            acc[1][0] += a.y * b.x; acc[1][1] += a.y * b.y; acc[1][2] += a.y * b.z; acc[1][3] += a.y * b.w;
            acc[2][0] += a.z * b.x; acc[2][1] += a.z * b.y; acc[2][2] += a.z * b.z; acc[2][3] += a.z * b.w;
            acc[3][0] += a.w * b.x; acc[3][1] += a.w * b.y; acc[3][2] += a.w * b.z; acc[3][3] += a.w * b.w;
        }
        __syncthreads();
    }

    #pragma unroll
    for (int i = 0; i < 4; i++) {
        int r = row0 + ty * 4 + i;
        if (r < N) {
            float4 o = make_float4(acc[i][0], acc[i][1], acc[i][2], acc[i][3]);
            *(float4*)&h[(size_t)r * HDIM + tx * 4] = o;
        }
    }
}

// a_s[r] = h[r,:] . att_s ; a_d[r] = h[r,:] . att_d.  16 lanes per row.
__global__ void k_attn_coef(const float* __restrict__ h,
                            const float* __restrict__ att_s,
                            const float* __restrict__ att_d, int N) {
    __shared__ float4 ss[16], sd[16];
    if (threadIdx.x < 16) {
        ss[threadIdx.x] = ((const float4*)att_s)[threadIdx.x];
        sd[threadIdx.x] = ((const float4*)att_d)[threadIdx.x];
    }
    __syncthreads();
    int t = blockIdx.x * blockDim.x + threadIdx.x;
    int r = t >> 4;
    int l = t & 15;
    if (r >= N) return;
    float4 v  = *(const float4*)&h[(size_t)r * HDIM + l * 4];
    float4 s4 = ss[l];
    float4 d4 = sd[l];
    float s = v.x * s4.x + v.y * s4.y + v.z * s4.z + v.w * s4.w;
    float d = v.x * d4.x + v.y * d4.y + v.z * d4.z + v.w * d4.w;
    #pragma unroll
    for (int off = 8; off > 0; off >>= 1) {
        s += __shfl_down_sync(0xffffffffu, s, off, 16);
        d += __shfl_down_sync(0xffffffffu, d, off, 16);
    }
    if (l == 0) { g_as[r] = s; g_ad[r] = d; }
}

// Fused edge-softmax + aggregation: one warp per destination node.
// No atomics: pure gather over the CSR in-edge list.
__global__ __launch_bounds__(256) void k_fused_agg(const float* __restrict__ h,
                                                   const float* __restrict__ bias,
                                                   float* __restrict__ out, int N) {
    const int warp = (blockIdx.x * blockDim.x + threadIdx.x) >> 5;
    const int lane = threadIdx.x & 31;
    if (warp >= N) return;
    const int d    = warp;
    const int base = g_off[d];
    const int deg  = g_off[d + 1] - base;     // >= 1 (self loop)
    const float ad_d = g_ad[d];

    float acc0 = 0.f, acc1 = 0.f;

    if (deg <= 32) {
        // register-resident path (covers ~all nodes; avg degree ~17)
        int   s = 0;
        float e = -CUDART_INF_F;
        if (lane < deg) {
            s = g_csrc[base + lane];
            float t = g_as[s] + ad_d;
            e = t >= 0.f ? t : NEG_SLOPE * t;
        }
        float m = e;
        #pragma unroll
        for (int o = 16; o > 0; o >>= 1) m = fmaxf(m, __shfl_xor_sync(0xffffffffu, m, o));
        float w = (lane < deg) ? __expf(e - m) : 0.f;
        float sum = w;
        #pragma unroll
        for (int o = 16; o > 0; o >>= 1) sum += __shfl_xor_sync(0xffffffffu, sum, o);
        const float inv = 1.f / sum;
        for (int j = 0; j < deg; j++) {
            int   sj = __shfl_sync(0xffffffffu, s, j);
            float al = __shfl_sync(0xffffffffu, w, j) * inv;
            acc0 += al * h[(size_t)sj * HDIM + lane];
            acc1 += al * h[(size_t)sj * HDIM + 32 + lane];
        }
    } else {
        float m = -CUDART_INF_F;
        for (int j = lane; j < deg; j += 32) {
            int s = g_csrc[base + j];
            float t = g_as[s] + ad_d;
            t = t >= 0.f ? t : NEG_SLOPE * t;
            g_ew[base + j] = t;
            m = fmaxf(m, t);
        }
        #pragma unroll
        for (int o = 16; o > 0; o >>= 1) m = fmaxf(m, __shfl_xor_sync(0xffffffffu, m, o));
        float sum = 0.f;
        for (int j = lane; j < deg; j += 32) {
            float w = __expf(g_ew[base + j] - m);
            g_ew[base + j] = w;
            sum += w;
        }
        #pragma unroll
        for (int o = 16; o > 0; o >>= 1) sum += __shfl_xor_sync(0xffffffffu, sum, o);
        const float inv = 1.f / sum;
        __syncwarp();
        for (int j = 0; j < deg; j++) {
            int   sj = g_csrc[base + j];      // broadcast loads
            float al = g_ew[base + j] * inv;
            acc0 += al * h[(size_t)sj * HDIM + lane];
            acc1 += al * h[(size_t)sj * HDIM + 32 + lane];
        }
    }

    out[(size_t)d * HDIM + lane]      = acc0 + bias[lane];
    out[(size_t)d * HDIM + 32 + lane] = acc1 + bias[32 + lane];
}

// Fused mean-pool (batch is sorted) + linear head. One 64-thread block per graph.
__global__ __launch_bounds__(64) void k_poolhead(const float* __restrict__ h,
                                                 const float* __restrict__ Wlin,
                                                 const float* __restrict__ blin,
                                                 float* __restrict__ out, int N) {
    __shared__ float red0[2], red1[2];
    const int g = blockIdx.x;
    const int c = threadIdx.x;

    // lower_bound(g) and lower_bound(g+1) over sorted g_batch
    int lo = 0, hi = N;
    while (lo < hi) { int mid = (lo + hi) >> 1; if (g_batch[mid] < g) lo = mid + 1; else hi = mid; }
    const int start = lo;
    lo = start; hi = N;
    while (lo < hi) { int mid = (lo + hi) >> 1; if (g_batch[mid] < g + 1) lo = mid + 1; else hi = mid; }
    const int end = lo;
    const int cnt = end - start;

    float acc = 0.f;
    for (int r = start; r < end; r++)
        acc += fmaxf(h[(size_t)r * HDIM + c], 0.f);
    const float p = acc / (float)(cnt > 0 ? cnt : 1);

    float s0 = p * Wlin[c * 2 + 0];
    float s1 = p * Wlin[c * 2 + 1];
    #pragma unroll
    for (int o = 16; o > 0; o >>= 1) {
        s0 += __shfl_xor_sync(0xffffffffu, s0, o);
        s1 += __shfl_xor_sync(0xffffffffu, s1, o);
    }
    if ((c & 31) == 0) { red0[c >> 5] = s0; red1[c >> 5] = s1; }
    __syncthreads();
    if (c == 0) {
        out[g * 2 + 0] = red0[0] + red0[1] + blin[0];
        out[g * 2 + 1] = red1[0] + red1[1] + blin[1];
    }
}

// ---------------- launch ----------------
extern "C" void kernel_launch(void* const* d_in, const int* in_sizes, int n_in,
                              void* d_out, int out_size) {
    const float* x    = (const float*)d_in[0];
    const void*  ei   = d_in[1];
    const void*  batch= d_in[2];
    const float* W1   = (const float*)d_in[3];
    const float* asr1 = (const float*)d_in[4];
    const float* adt1 = (const float*)d_in[5];
    const float* b1   = (const float*)d_in[6];
    const float* W2   = (const float*)d_in[7];
    const float* asr2 = (const float*)d_in[8];
    const float* adt2 = (const float*)d_in[9];
    const float* b2   = (const float*)d_in[10];
    const float* Wlin = (const float*)d_in[11];
    const float* blin = (const float*)d_in[12];
    float* out = (float*)d_out;

    const int N = in_sizes[2];            // batch length
    const int E = in_sizes[1] / 2;        // edge_index has 2*E elements
    const int Etot = E + N;

    float* h1   = (float*)g_h1v;
    float* out1 = (float*)g_out1v;
    float* h2   = (float*)g_h2v;
    float* out2 = (float*)g_out2v;

    const int T = 256;
    dim3 gN((N + T - 1) / T);
    dim3 gEt((Etot + T - 1) / T);
    dim3 gGemm((N + 63) / 64);
    dim3 gRow16((N * 16 + T - 1) / T);
    dim3 gWarpN((N * 32 + T - 1) / T);

    // ---- graph preprocessing (once; reused by both layers) ----
    k_detect<<<1, 256>>>((const int*)ei, E);
    k_zero_deg<<<gN, T>>>(N);
    k_prep<<<gEt, T>>>(ei, batch, E, N);
    k_scan<<<1, 1024>>>(N);
    k_scatter<<<gEt, T>>>(E, N);

    // ---- layer 1 ----
    k_gemm64<false><<<gGemm, T>>>(x, W1, h1, N, FIN);
    k_attn_coef<<<gRow16, T>>>(h1, asr1, adt1, N);
    k_fused_agg<<<gWarpN, T>>>(h1, b1, out1, N);

    // ---- layer 2 (relu fused into GEMM input) ----
    k_gemm64<true><<<gGemm, T>>>(out1, W2, h2, N, HDIM);
    k_attn_coef<<<gRow16, T>>>(h2, asr2, adt2, N);
    k_fused_agg<<<gWarpN, T>>>(h2, b2, out2, N);

    // ---- pool + head (relu fused) ----
    k_poolhead<<<NGRAPH, 64>>>(out2, Wlin, blin, out, N);
}